// round 3
// baseline (speedup 1.0000x reference)
#include <cuda_runtime.h>
#include <cstdint>

// Screen / tiling constants (W=1280, H=720 are exact multiples of L=16)
#define W_SCREEN 1280.0f
#define H_SCREEN 720.0f
#define NBW      80
#define NBH      45
#define N_POINTS 32768

// Fused kernel: one block per (1024-point chunk, xi column).
// Each thread owns 8 points split as two groups of 4 consecutive points
// (group B offset +512) so every warp STG.128 covers 512 contiguous,
// fully-written bytes. Per point we precompute the valid tile-row interval
// [a, a+n) (n = 0 when the xi column misses the point's AABB), then sweep
// yi = 0..44 with a single unsigned range-compare per point per row.
//
// Reference condition per (tile, point):
//   min(xmax,right) > max(xmin,left) && min(ymax,bottom) > max(ymin,top)
// With right=left+16, bottom=top+16 exact and xmax>xmin, ymax>ymin
// guaranteed (radius >= 1), this reduces to the separable interval test.
__global__ __launch_bounds__(128) void fused_mask_kernel(
        const float* __restrict__ pos2d,
        const float* __restrict__ radius,
        float* __restrict__ out) {
    int t     = threadIdx.x;        // 0..127
    int chunk = blockIdx.x;         // 0..31  (1024 points per chunk)
    int xi    = blockIdx.y;         // 0..79
    int left  = xi * 16;
    int right = left + 16;

    int pA = chunk * 1024 + t * 4;  // group A: 4 consecutive points
    // group B: pA + 512

    unsigned a[8], n[8];

#pragma unroll
    for (int g = 0; g < 2; g++) {
        int p = pA + g * 512;
        float4 q01 = reinterpret_cast<const float4*>(pos2d)[p / 2];      // pts p, p+1
        float4 q23 = reinterpret_cast<const float4*>(pos2d)[p / 2 + 1];  // pts p+2, p+3
        float4 r4  = reinterpret_cast<const float4*>(radius)[p / 4];

        float xs[4] = {q01.x, q01.z, q23.x, q23.z};
        float ys[4] = {q01.y, q01.w, q23.y, q23.w};
        float rs[4] = {r4.x, r4.y, r4.z, r4.w};
#pragma unroll
        for (int j = 0; j < 4; j++) {
            float x = xs[j], y = ys[j], r = rs[j];
            int xmin = (int)fminf(fmaxf(x - r, 0.0f), W_SCREEN);
            int xmax = (int)fminf(fmaxf(x + r, 0.0f), W_SCREEN);
            int ymin = (int)fminf(fmaxf(y - r, 0.0f), H_SCREEN);
            int ymax = (int)fminf(fmaxf(y + r, 0.0f), H_SCREEN);

            bool okx = (xmax > left) && (xmin < right);
            unsigned aj = (unsigned)(ymin >> 4);                 // first valid yi
            unsigned bj = (unsigned)(((ymax - 1) >> 4) + 1);     // one past last
            a[g * 4 + j] = aj;
            n[g * 4 + j] = okx ? (bj - aj) : 0u;                 // interval length
        }
    }

    float* outA = out + (size_t)xi * NBH * N_POINTS + pA;
    float* outB = outA + 512;

#pragma unroll 5
    for (int yi = 0; yi < NBH; yi++) {
        float4 vA, vB;
        vA.x = ((unsigned)(yi - a[0]) < n[0]) ? 1.0f : 0.0f;
        vA.y = ((unsigned)(yi - a[1]) < n[1]) ? 1.0f : 0.0f;
        vA.z = ((unsigned)(yi - a[2]) < n[2]) ? 1.0f : 0.0f;
        vA.w = ((unsigned)(yi - a[3]) < n[3]) ? 1.0f : 0.0f;
        vB.x = ((unsigned)(yi - a[4]) < n[4]) ? 1.0f : 0.0f;
        vB.y = ((unsigned)(yi - a[5]) < n[5]) ? 1.0f : 0.0f;
        vB.z = ((unsigned)(yi - a[6]) < n[6]) ? 1.0f : 0.0f;
        vB.w = ((unsigned)(yi - a[7]) < n[7]) ? 1.0f : 0.0f;
        *reinterpret_cast<float4*>(outA) = vA;
        *reinterpret_cast<float4*>(outB) = vB;
        outA += N_POINTS;
        outB += N_POINTS;
    }
}

extern "C" void kernel_launch(void* const* d_in, const int* in_sizes, int n_in,
                              void* d_out, int out_size) {
    const float* pos2d  = (const float*)d_in[0];   // [32768, 2] float32
    const float* radius = (const float*)d_in[1];   // [32768]    float32
    float* out          = (float*)d_out;           // [3600, 32768] float32

    dim3 grid(32, NBW);                            // 32 chunks x 80 xi columns
    fused_mask_kernel<<<grid, 128>>>(pos2d, radius, out);
}

// round 4
// speedup vs baseline: 1.1729x; 1.1729x over previous
#include <cuda_runtime.h>
#include <cstdint>

// Screen / tiling constants (W=1280, H=720 are exact multiples of L=16)
#define W_SCREEN 1280.0f
#define H_SCREEN 720.0f
#define NBW      80
#define NBH      45
#define N_POINTS 32768

// Single fused kernel, R2 work partitioning: one block per (512-point chunk,
// xi column); each thread owns 4 consecutive points and sweeps yi = 0..44
// emitting one float4 (STG.128) per row. The per-point AABB -> tile-row
// interval [a, a+n) is computed in the prolog directly from pos2d/radius
// (n = 0 when this xi column misses the point's x-interval).
//
// Reference condition per (tile, point):
//   min(xmax,right) > max(xmin,left) && min(ymax,bottom) > max(ymin,top)
// With right=left+16, bottom=top+16 exact (W,H multiples of 16) and
// xmax>xmin, ymax>ymin guaranteed (radius >= 1), this reduces to the
// separable interval test; the y part becomes (unsigned)(yi - a) < n.
__global__ __launch_bounds__(128) void fused_mask_kernel(
        const float* __restrict__ pos2d,
        const float* __restrict__ radius,
        float* __restrict__ out) {
    int g  = blockIdx.x * 128 + threadIdx.x;   // 4-point group, 0..8191
    int xi = blockIdx.y;                       // 0..79
    int left  = xi * 16;
    int right = left + 16;

    // Load this thread's 4 points (48 bytes, fully coalesced per warp).
    float4 q01 = reinterpret_cast<const float4*>(pos2d)[2 * g];      // pts 4g,4g+1
    float4 q23 = reinterpret_cast<const float4*>(pos2d)[2 * g + 1];  // pts 4g+2,4g+3
    float4 r4  = reinterpret_cast<const float4*>(radius)[g];

    unsigned a[4], n[4];
    {
        float xs[4] = {q01.x, q01.z, q23.x, q23.z};
        float ys[4] = {q01.y, q01.w, q23.y, q23.w};
        float rs[4] = {r4.x, r4.y, r4.z, r4.w};
#pragma unroll
        for (int j = 0; j < 4; j++) {
            float x = xs[j], y = ys[j], r = rs[j];
            int xmin = (int)fminf(fmaxf(x - r, 0.0f), W_SCREEN);
            int xmax = (int)fminf(fmaxf(x + r, 0.0f), W_SCREEN);
            int ymin = (int)fminf(fmaxf(y - r, 0.0f), H_SCREEN);
            int ymax = (int)fminf(fmaxf(y + r, 0.0f), H_SCREEN);

            bool okx = (xmax > left) && (xmin < right);
            unsigned aj = (unsigned)(ymin >> 4);               // first valid yi
            unsigned bj = (unsigned)(((ymax - 1) >> 4) + 1);   // one past last
            a[j] = aj;
            n[j] = okx ? (bj - aj) : 0u;                       // interval length
        }
    }

    float* optr = out + (size_t)xi * NBH * N_POINTS + (size_t)g * 4;

#pragma unroll 5
    for (int yi = 0; yi < NBH; yi++) {
        float4 v;
        v.x = ((unsigned)(yi - a[0]) < n[0]) ? 1.0f : 0.0f;
        v.y = ((unsigned)(yi - a[1]) < n[1]) ? 1.0f : 0.0f;
        v.z = ((unsigned)(yi - a[2]) < n[2]) ? 1.0f : 0.0f;
        v.w = ((unsigned)(yi - a[3]) < n[3]) ? 1.0f : 0.0f;
        *reinterpret_cast<float4*>(optr) = v;
        optr += N_POINTS;
    }
}

extern "C" void kernel_launch(void* const* d_in, const int* in_sizes, int n_in,
                              void* d_out, int out_size) {
    const float* pos2d  = (const float*)d_in[0];   // [32768, 2] float32
    const float* radius = (const float*)d_in[1];   // [32768]    float32
    float* out          = (float*)d_out;           // [3600, 32768] float32

    dim3 grid(64, NBW);                            // 64 chunks x 80 xi columns
    fused_mask_kernel<<<grid, 128>>>(pos2d, radius, out);
}

// round 6
// speedup vs baseline: 1.2393x; 1.0567x over previous
#include <cuda_runtime.h>
#include <cstdint>

// Screen / tiling constants (W=1280, H=720 are exact multiples of L=16)
#define W_SCREEN 1280.0f
#define H_SCREEN 720.0f
#define NBW      80
#define NBH      45
#define N_POINTS 32768
#define ROWS_PER_CTA 9     // 45 = 5 * 9

// Fused kernel, fine-grained work items to kill the wave-quantization tail:
// one block per (512-point chunk, xi column, 9-row band). Each thread owns 4
// consecutive points, computes their AABB -> tile-row interval [a, a+n) in
// the prolog (n = 0 when this xi column misses the point's x-interval), then
// sweeps its 9 rows emitting one float4 (STG.128) per row.
//
// Reference condition per (tile, point):
//   min(xmax,right) > max(xmin,left) && min(ymax,bottom) > max(ymin,top)
// With right=left+16, bottom=top+16 exact (W,H multiples of 16) and
// xmax>xmin, ymax>ymin guaranteed (radius >= 1), this reduces to the
// separable interval test; the y part becomes (unsigned)(yi - a) < n.
__global__ __launch_bounds__(128) void fused_mask_kernel(
        const float* __restrict__ pos2d,
        const float* __restrict__ radius,
        float* __restrict__ out) {
    int g  = blockIdx.x * 128 + threadIdx.x;   // 4-point group, 0..8191
    int xi = blockIdx.y;                       // 0..79
    int y0 = blockIdx.z * ROWS_PER_CTA;        // 0, 9, 18, 27, 36
    int left  = xi * 16;
    int right = left + 16;

    // Load this thread's 4 points (48 bytes, fully coalesced; L2-resident).
    float4 q01 = reinterpret_cast<const float4*>(pos2d)[2 * g];      // pts 4g,4g+1
    float4 q23 = reinterpret_cast<const float4*>(pos2d)[2 * g + 1];  // pts 4g+2,4g+3
    float4 r4  = reinterpret_cast<const float4*>(radius)[g];

    unsigned a[4], n[4];
    {
        float xs[4] = {q01.x, q01.z, q23.x, q23.z};
        float ys[4] = {q01.y, q01.w, q23.y, q23.w};
        float rs[4] = {r4.x, r4.y, r4.z, r4.w};
#pragma unroll
        for (int j = 0; j < 4; j++) {
            float x = xs[j], y = ys[j], r = rs[j];
            int xmin = (int)fminf(fmaxf(x - r, 0.0f), W_SCREEN);
            int xmax = (int)fminf(fmaxf(x + r, 0.0f), W_SCREEN);
            int ymin = (int)fminf(fmaxf(y - r, 0.0f), H_SCREEN);
            int ymax = (int)fminf(fmaxf(y + r, 0.0f), H_SCREEN);

            bool okx = (xmax > left) && (xmin < right);
            unsigned aj = (unsigned)(ymin >> 4);               // first valid yi
            unsigned bj = (unsigned)(((ymax - 1) >> 4) + 1);   // one past last
            a[j] = aj;
            n[j] = okx ? (bj - aj) : 0u;                       // interval length
        }
    }

    float* optr = out + ((size_t)xi * NBH + y0) * N_POINTS + (size_t)g * 4;

#pragma unroll
    for (int k = 0; k < ROWS_PER_CTA; k++) {
        int yi = y0 + k;
        float4 v;
        v.x = ((unsigned)(yi - a[0]) < n[0]) ? 1.0f : 0.0f;
        v.y = ((unsigned)(yi - a[1]) < n[1]) ? 1.0f : 0.0f;
        v.z = ((unsigned)(yi - a[2]) < n[2]) ? 1.0f : 0.0f;
        v.w = ((unsigned)(yi - a[3]) < n[3]) ? 1.0f : 0.0f;
        *reinterpret_cast<float4*>(optr) = v;
        optr += N_POINTS;
    }
}

extern "C" void kernel_launch(void* const* d_in, const int* in_sizes, int n_in,
                              void* d_out, int out_size) {
    const float* pos2d  = (const float*)d_in[0];   // [32768, 2] float32
    const float* radius = (const float*)d_in[1];   // [32768]    float32
    float* out          = (float*)d_out;           // [3600, 32768] float32

    dim3 grid(64, NBW, NBH / ROWS_PER_CTA);        // 64 chunks x 80 xi x 5 bands
    fused_mask_kernel<<<grid, 128>>>(pos2d, radius, out);
}